// round 17
// baseline (speedup 1.0000x reference)
#include <cuda_runtime.h>

// Problem constants
#define NN 512
#define KK 17
#define WW 48
#define HH 64
#define NK (NN * KK)                       // 8704
#define HMSZ (HH * WW)                     // 3072 floats
#define TOTAL ((double)NN * KK * HH * WW)  // 26738688

#define GRID 592                           // 148 SMs * 4 (or 5) blocks, single wave
#define NWARP 8                            // warps per block (256 threads)
#define GWARPS (GRID * NWARP)              // 4736 warps total
#define FULL 0xFFFFFFFFu

__device__ double g_acc;          // zero-init; reset by last block each run
__device__ unsigned int g_cnt;    // ditto

__global__ __launch_bounds__(256, 5) void loss_kernel(
    const float* __restrict__ pred,      // [N,K,2]
    const float* __restrict__ sigma,     // [N,K,2]
    const float* __restrict__ teacher,   // [N,K,H,W]
    const float* __restrict__ twgt,      // [N,K,1]
    float* __restrict__ out)             // [1]
{
    const int tid  = threadIdx.x;
    const int wid  = tid >> 5;
    const int lane = tid & 31;
    // Transposed global warp id: uniform per-SM work mix.
    const int gw   = wid * GRID + blockIdx.x;

    const float2* __restrict__ pred2  = (const float2*)pred;
    const float2* __restrict__ sigma2 = (const float2*)sigma;

    // Lane-private table base: this lane owns ex quad-column (lane % 12).
    const float exbase = (float)(4 * (lane % 12));

    float acc = 0.0f;

    // ---- Prime params for first heatmap ----
    float2 pr, sg;
    float  tv;
    if (gw < NK) {
        pr = pred2[gw];
        sg = sigma2[gw];
        tv = twgt[gw];
    } else {
        pr = make_float2(0.f, 0.f); sg = make_float2(1.f, 1.f); tv = 0.f;
    }

    for (int nk = gw; nk < NK; nk += GWARPS) {
        // ---- Prefetch NEXT heatmap's params (land during current stream) ----
        const int nk2 = nk + GWARPS;
        float2 prn, sgn;
        float  tvn;
        if (nk2 < NK) {
            prn = pred2[nk2];
            sgn = sigma2[nk2];
            tvn = twgt[nk2];
        } else {
            prn = make_float2(0.f, 0.f); sgn = make_float2(1.f, 1.f); tvn = 0.f;
        }

        // ---- Register-resident tables (no smem, no syncwarp) ----
        const float mux = pr.x * (float)WW;
        const float muy = pr.y * (float)HH;
        const float sx  = sg.x;
        const float sy  = sg.y;
        const float m = ((mux - 3.0f * sx < (float)WW) &&
                         (muy - 3.0f * sy < (float)HH) &&
                         (mux + 3.0f * sx + 1.0f >= 0.0f) &&
                         (muy + 3.0f * sy + 1.0f >= 0.0f)) ? 1.0f : 0.0f;
        const float tw   = tv * m;
        const float coef = tw * tw;
        const float invx = 1.0f / (sx * sx + 1e-9f);
        const float invy = 1.0f / (sy * sy + 1e-9f);

        float dx0 = exbase + 0.0f - mux;
        float dx1 = exbase + 1.0f - mux;
        float dx2 = exbase + 2.0f - mux;
        float dx3 = exbase + 3.0f - mux;
        const float ex0 = __expf(-0.5f * dx0 * dx0 * invx);
        const float ex1 = __expf(-0.5f * dx1 * dx1 * invx);
        const float ex2 = __expf(-0.5f * dx2 * dx2 * invx);
        const float ex3 = __expf(-0.5f * dx3 * dx3 * invx);

        float dyA = (float)lane - muy;
        float dyB = (float)(lane + 32) - muy;
        const float eyA = __expf(-0.5f * dyA * dyA * invy);
        const float eyB = __expf(-0.5f * dyB * dyB * invy);

        // ---- Stream this warp's heatmap: 24 float4 per lane, barrier-free ----
        const float4* __restrict__ tp =
            reinterpret_cast<const float4*>(teacher + (size_t)nk * HMSZ);

        float wsum = 0.0f;
#pragma unroll 6
        for (int k = 0; k < 24; k++) {
            const int q = lane + 32 * k;   // quad index 0..767
            const float4 t = tp[q];
            const int h = q / 12;          // 12 quads per row (W=48), h in 0..63
            const int c = q - 12 * h;      // quad column 0..11

            // ey[h]: shfl idx wraps mod 32 per PTX spec; select A/B half.
            const float ylo = __shfl_sync(FULL, eyA, h);
            const float yhi = __shfl_sync(FULL, eyB, h);
            const float y   = (h < 32) ? ylo : yhi;

            // ex quad-column c from lane c (lanes 0..11 authoritative).
            const float e0 = __shfl_sync(FULL, ex0, c);
            const float e1 = __shfl_sync(FULL, ex1, c);
            const float e2 = __shfl_sync(FULL, ex2, c);
            const float e3 = __shfl_sync(FULL, ex3, c);

            float d0 = e0 * y - t.x;
            float d1 = e1 * y - t.y;
            float d2 = e2 * y - t.z;
            float d3 = e3 * y - t.w;
            wsum += d0 * d0 + d1 * d1 + d2 * d2 + d3 * d3;
        }
        acc += wsum * coef;

        // ---- Shift param pipeline ----
        pr = prn; sg = sgn; tv = tvn;
    }

    // ---- Block reduce (single __syncthreads in the kernel) ----
    __shared__ float s_warp[NWARP];
#pragma unroll
    for (int off = 16; off > 0; off >>= 1)
        acc += __shfl_down_sync(FULL, acc, off);
    if (lane == 0) s_warp[wid] = acc;
    __syncthreads();

    if (tid < NWARP) {
        float v = s_warp[tid];
#pragma unroll
        for (int off = NWARP / 2; off > 0; off >>= 1)
            v += __shfl_down_sync((1u << NWARP) - 1u, v, off);
        if (tid == 0) {
            atomicAdd(&g_acc, (double)v);
            __threadfence();
            unsigned int ticket = atomicAdd(&g_cnt, 1u);
            if (ticket == GRID - 1) {
                double total = atomicAdd(&g_acc, 0.0);   // coherent read
                out[0] = (float)(total / TOTAL);         // LOSS_WEIGHT = 1.0
                g_acc = 0.0;                             // reset for next replay
                g_cnt = 0u;
            }
        }
    }
}

extern "C" void kernel_launch(void* const* d_in, const int* in_sizes, int n_in,
                              void* d_out, int out_size) {
    const float* pred    = (const float*)d_in[0];
    const float* sigma   = (const float*)d_in[1];
    const float* teacher = (const float*)d_in[2];
    const float* twgt    = (const float*)d_in[3];
    float* out = (float*)d_out;

    loss_kernel<<<GRID, 256>>>(pred, sigma, teacher, twgt, out);
}